// round 4
// baseline (speedup 1.0000x reference)
#include <cuda_runtime.h>

// ---------------- problem constants ----------------
#define BB  8
#define SEQ 32768
#define HH  96
#define GG  384        // 4*HH
#define KW  16         // progress granularity (timesteps)
#define HC  512        // head chunk
#define NT  768        // threads per CTA (24 warps)

typedef unsigned long long ull;

// ---------------- scratch ----------------
__device__ float g_h0seq[(size_t)BB * SEQ * HH];
__device__ float g_xp1 [(size_t)BB * SEQ * GG];
__device__ float g_h1seq[(size_t)BB * SEQ * HH];

__device__ int g_prog0[BB];
__device__ int g_progx[2 * BB];
__device__ int g_prog1[BB];

// ---------------- packed f32x2 helpers ----------------
__device__ __forceinline__ ull ffma2(ull a, ull b, ull c) {
    ull d;
    asm("fma.rn.f32x2 %0, %1, %2, %3;" : "=l"(d) : "l"(a), "l"(b), "l"(c));
    return d;
}
__device__ __forceinline__ void unpack2(ull v, float& x, float& y) {
    asm("mov.b64 {%0, %1}, %2;" : "=f"(x), "=f"(y) : "l"(v));
}

__device__ __forceinline__ float tanh_f(float x) {
    float e = __expf(2.0f * x);
    return 1.0f - __fdividef(2.0f, 1.0f + e);
}

// load 48-float half-row into 24 f32x2 regs
__device__ __forceinline__ void load_half(ull* w, const float* rowp) {
    const ulonglong2* wp = (const ulonglong2*)rowp;
#pragma unroll
    for (int k = 0; k < 12; k++) {
        ulonglong2 v = __ldg(wp + k);
        w[2 * k]     = v.x;
        w[2 * k + 1] = v.y;
    }
}

// half-dot: 48 elements, two 12-deep chains
__device__ __forceinline__ float half_dot(const ull* __restrict__ w,
                                          const float* __restrict__ hsh) {
    ull a0 = 0ull, a1 = 0ull;
    const ulonglong2* h4 = (const ulonglong2*)hsh;
#pragma unroll
    for (int k = 0; k < 12; k++) {
        ulonglong2 hv = h4[k];
        a0 = ffma2(w[2 * k],     hv.x, a0);
        a1 = ffma2(w[2 * k + 1], hv.y, a1);
    }
    float x0, y0, x1, y1;
    unpack2(a0, x0, y0);
    unpack2(a1, x1, y1);
    return (x0 + x1) + (y0 + y1);
}

__device__ __forceinline__ float pick4(int m, float a0, float a1, float a2, float a3) {
    return (m == 0) ? a0 : ((m == 1) ? a1 : ((m == 2) ? a2 : a3));
}

__device__ __forceinline__ void wait_ge(int* p, int target) {
    while (atomicAdd(p, 0) < target) { __nanosleep(64); }
    __threadfence();
}

__global__ void reset_kernel() {
    int i = threadIdx.x;
    if (i < BB)     g_prog0[i] = 0;
    if (i < 2 * BB) g_progx[i] = 0;
    if (i < BB)     g_prog1[i] = 0;
}

// =====================================================================
// Mega-kernel: 40 blocks x 768 threads.
//   0..7   : layer-0 recurrence (1 batch each)
//   8..23  : xp1 workers (2 per batch, parity interleave)
//   24..31 : layer-1 recurrence (1 batch each)
//   32..39 : head workers (1 per batch)
//
// Recurrence lane mapping (warp w of 24, lane l):
//   unit j = 4*w + (l>>3)   (0..95)
//   gate q = (l>>1) & 3     (0 i, 1 f, 2 g, 3 o)
//   half  = l & 1           (h[0:48) vs h[48:96))
//   row r = q*96 + j
// =====================================================================
__global__ void __launch_bounds__(NT, 1)
mega_kernel(const float* __restrict__ x,
            const float* __restrict__ Wih0, const float* __restrict__ Whh0,
            const float* __restrict__ bv0,
            const float* __restrict__ Wih1, const float* __restrict__ Whh1,
            const float* __restrict__ bv1,
            const float* __restrict__ h0in, const float* __restrict__ c0in,
            const float* __restrict__ head_w, const float* __restrict__ head_b,
            float* __restrict__ out)
{
    __shared__ __align__(16) float sh[KW * HH];   // 6 KB; recurrences use first 2*HH
    const int bid = blockIdx.x;
    const int g   = threadIdx.x;

    if (bid < 8) {
        // ======== layer-0 recurrence ========
        const int b    = bid;
        const int wid  = g >> 5, l = g & 31;
        const int j    = (wid << 2) + (l >> 3);
        const int q    = (l >> 1) & 3;
        const int half = l & 1;
        const int r    = q * HH + j;

        ull w[24];
        load_half(w, Whh0 + r * HH + 48 * half);
        const float wih  = __ldg(&Wih0[r]);
        const float bias = __ldg(&bv0[r]);
        const float s_ = (q == 2) ? 2.0f : 1.0f;
        const float d_ = (q == 2) ? -1.0f : 0.0f;
        const int hoff = 48 * half;

        float c = __ldg(&c0in[j]);
        if (g < HH) sh[g] = __ldg(&h0in[g]);
        __syncthreads();

        const float* xb = x + (size_t)b * SEQ;
        float* hb_t = g_h0seq + (size_t)b * SEQ * HH;
        float xnext = __ldg(&xb[0]);

#pragma unroll 1
        for (int t = 0; t < SEQ; t++) {
            const float* hr = sh + (t & 1) * HH;
            float*       hw = sh + ((t + 1) & 1) * HH;
            float xt = xnext;
            xnext = __ldg(&xb[min(t + 1, SEQ - 1)]);

            float s  = half_dot(w, hr + hoff);
            float dot = s + __shfl_xor_sync(0xFFFFFFFFu, s, 1) + fmaf(xt, wih, bias);

            float e   = __expf(-s_ * dot);
            float act = __fdividef(s_, 1.0f + e) + d_;

            float x2 = __shfl_xor_sync(0xFFFFFFFFu, act, 2);
            float x4 = __shfl_xor_sync(0xFFFFFFFFu, act, 4);
            float x6 = __shfl_xor_sync(0xFFFFFFFFu, act, 6);
            float iv = pick4(q,     act, x2, x4, x6);
            float fv = pick4(q ^ 1, act, x2, x4, x6);
            float gv = pick4(q ^ 2, act, x2, x4, x6);
            float ov = pick4(q ^ 3, act, x2, x4, x6);

            c = fmaf(fv, c, iv * gv);
            float hval = ov * tanh_f(c);
            if ((l & 7) == 0) {
                hw[j]   = hval;
                hb_t[j] = hval;
            }
            __syncthreads();
            if (((t & (KW - 1)) == (KW - 1)) && g == 0) {
                __threadfence();
                atomicExch(&g_prog0[b], t + 1);
            }
            hb_t += HH;
        }
    } else if (bid < 24) {
        // ======== xp1 workers: lane pairs, halves ========
        const int i    = bid - 8;
        const int b    = i >> 1;
        const int par  = i & 1;
        const int row  = g >> 1;       // 0..383
        const int half = g & 1;

        ull w[24];
        load_half(w, Wih1 + row * HH + 48 * half);
        const float bias = __ldg(&bv1[row]);
        const int hoff = 48 * half;

        const float* hbase = g_h0seq + (size_t)b * SEQ * HH;
        float* xpb = g_xp1 + (size_t)b * SEQ * GG;

#pragma unroll 1
        for (int t0 = par * KW; t0 < SEQ; t0 += 2 * KW) {
            if (g == 0) wait_ge(&g_prog0[b], t0 + KW);
            __syncthreads();
            if (g < 384)
                ((float4*)sh)[g] = ((const float4*)(hbase + (size_t)t0 * HH))[g];
            __syncthreads();
            float* xpt = xpb + (size_t)t0 * GG + row;
#pragma unroll 4
            for (int s = 0; s < KW; s++) {
                float sv  = half_dot(w, sh + s * HH + hoff);
                float dot = sv + __shfl_xor_sync(0xFFFFFFFFu, sv, 1) + bias;
                if (!half) xpt[0] = dot;
                xpt += GG;
            }
            __syncthreads();
            if (g == 0) {
                __threadfence();
                atomicExch(&g_progx[par * BB + b], t0 + KW);
            }
        }
    } else if (bid < 32) {
        // ======== layer-1 recurrence ========
        const int b    = bid - 24;
        const int wid  = g >> 5, l = g & 31;
        const int j    = (wid << 2) + (l >> 3);
        const int q    = (l >> 1) & 3;
        const int half = l & 1;
        const int r    = q * HH + j;

        ull w[24];
        load_half(w, Whh1 + r * HH + 48 * half);
        const float s_ = (q == 2) ? 2.0f : 1.0f;
        const float d_ = (q == 2) ? -1.0f : 0.0f;
        const int hoff = 48 * half;

        float c = __ldg(&c0in[HH + j]);
        if (g < HH) sh[g] = __ldg(&h0in[HH + g]);
        __syncthreads();

        const float* xpr = g_xp1 + (size_t)b * SEQ * GG + r;   // row pointer
        float* hb_t = g_h1seq + (size_t)b * SEQ * HH;

#pragma unroll 1
        for (int t0 = 0; t0 < SEQ; t0 += KW) {
            const int par = (t0 / KW) & 1;
            if (g == 0) wait_ge(&g_progx[par * BB + b], t0 + KW);
            __syncthreads();

            float xpn = xpr[0];
#pragma unroll 1
            for (int tt = 0; tt < KW; tt++) {
                const int t = t0 + tt;
                const float* hr = sh + (t & 1) * HH;
                float*       hw = sh + ((t + 1) & 1) * HH;

                float xp = xpn;
                // prefetch next step, staying inside the ready chunk
                xpn = xpr[(tt + 1 < KW) ? GG : 0];

                float s  = half_dot(w, hr + hoff);
                float dot = s + __shfl_xor_sync(0xFFFFFFFFu, s, 1) + xp;

                float e   = __expf(-s_ * dot);
                float act = __fdividef(s_, 1.0f + e) + d_;

                float x2 = __shfl_xor_sync(0xFFFFFFFFu, act, 2);
                float x4 = __shfl_xor_sync(0xFFFFFFFFu, act, 4);
                float x6 = __shfl_xor_sync(0xFFFFFFFFu, act, 6);
                float iv = pick4(q,     act, x2, x4, x6);
                float fv = pick4(q ^ 1, act, x2, x4, x6);
                float gv = pick4(q ^ 2, act, x2, x4, x6);
                float ov = pick4(q ^ 3, act, x2, x4, x6);

                c = fmaf(fv, c, iv * gv);
                float hval = ov * tanh_f(c);
                if ((l & 7) == 0) {
                    hw[j]   = hval;
                    hb_t[j] = hval;
                }
                __syncthreads();
                hb_t += HH;
                xpr  += GG;
            }
            if (g == 0) {
                __threadfence();
                atomicExch(&g_prog1[b], t0 + KW);
            }
        }
    } else {
        // ======== head workers ========
        const int b = bid - 32;
        float4 wv[24];
        const float4* wp = (const float4*)head_w;
#pragma unroll
        for (int k = 0; k < 24; k++) wv[k] = __ldg(&wp[k]);
        const float hb0 = __ldg(&head_b[0]);
        const float* h1b = g_h1seq + (size_t)b * SEQ * HH;
        float* ob = out + (size_t)b * SEQ;

#pragma unroll 1
        for (int t0 = 0; t0 < SEQ; t0 += HC) {
            if (g == 0) wait_ge(&g_prog1[b], t0 + HC);
            __syncthreads();
            if (g < HC) {
                const float4* hp = (const float4*)(h1b + (size_t)(t0 + g) * HH);
                float acc = 0.0f;
#pragma unroll
                for (int k = 0; k < 24; k++) {
                    float4 a = hp[k];
                    acc += a.x * wv[k].x + a.y * wv[k].y + a.z * wv[k].z + a.w * wv[k].w;
                }
                ob[t0 + g] = acc + hb0;
            }
        }
    }
}

extern "C" void kernel_launch(void* const* d_in, const int* in_sizes, int n_in,
                              void* d_out, int out_size)
{
    (void)in_sizes; (void)n_in; (void)out_size;
    const float* x      = (const float*)d_in[0];
    const float* W_ih_0 = (const float*)d_in[1];
    const float* W_hh_0 = (const float*)d_in[2];
    const float* b_0    = (const float*)d_in[3];
    const float* W_ih_1 = (const float*)d_in[4];
    const float* W_hh_1 = (const float*)d_in[5];
    const float* b_1    = (const float*)d_in[6];
    const float* h0     = (const float*)d_in[7];
    const float* c0     = (const float*)d_in[8];
    const float* head_w = (const float*)d_in[9];
    const float* head_b = (const float*)d_in[10];
    float* out = (float*)d_out;

    reset_kernel<<<1, 32>>>();
    mega_kernel<<<40, NT>>>(x, W_ih_0, W_hh_0, b_0, W_ih_1, W_hh_1, b_1,
                            h0, c0, head_w, head_b, out);
}

// round 5
// speedup vs baseline: 1.4462x; 1.4462x over previous
#include <cuda_runtime.h>

// ---------------- problem constants ----------------
#define BB  8
#define SEQ 32768
#define HH  96
#define GG  384        // 4*HH
#define KW  16         // progress granularity (timesteps)
#define HC  256        // head chunk
#define NT  384        // threads per CTA

typedef unsigned long long ull;

// ---------------- scratch (device globals; allocation banned) ----------------
__device__ float g_h0seq[(size_t)BB * SEQ * HH];
__device__ float g_xp1 [(size_t)BB * SEQ * GG];
__device__ float g_h1seq[(size_t)BB * SEQ * HH];

__device__ int g_prog0[BB];
__device__ int g_progx[2 * BB];
__device__ int g_prog1[BB];

// ---------------- packed f32x2 helpers ----------------
__device__ __forceinline__ ull ffma2(ull a, ull b, ull c) {
    ull d;
    asm("fma.rn.f32x2 %0, %1, %2, %3;" : "=l"(d) : "l"(a), "l"(b), "l"(c));
    return d;
}
__device__ __forceinline__ ull pack2(float x, float y) {
    ull v;
    asm("mov.b64 %0, {%1, %2};" : "=l"(v) : "f"(x), "f"(y));
    return v;
}
__device__ __forceinline__ void unpack2(ull v, float& x, float& y) {
    asm("mov.b64 {%0, %1}, %2;" : "=f"(x), "=f"(y) : "l"(v));
}

// ---------------- fast activations ----------------
__device__ __forceinline__ float sigmoid_f(float x) {
    float e = __expf(-x);
    return __fdividef(1.0f, 1.0f + e);
}
__device__ __forceinline__ float tanh_f(float x) {
    float e = __expf(2.0f * x);
    return 1.0f - __fdividef(2.0f, 1.0f + e);
}

// ---------------- weight row -> registers ----------------
__device__ __forceinline__ void load_row(ull* w, const float* rowp) {
    const ulonglong2* wp = (const ulonglong2*)rowp;
#pragma unroll
    for (int k = 0; k < 24; k++) {
        ulonglong2 v = __ldg(wp + k);
        w[2 * k]     = v.x;
        w[2 * k + 1] = v.y;
    }
}

// dot(w_row, h[0..95]) + init ; h 16B aligned
__device__ __forceinline__ float dotv(const ull* __restrict__ w,
                                      const float* __restrict__ hsh,
                                      float init) {
    ull a0 = pack2(init, 0.0f);
    ull a1 = 0ull;
    const ulonglong2* h4 = (const ulonglong2*)hsh;
#pragma unroll
    for (int k = 0; k < 24; k++) {
        ulonglong2 hv = h4[k];
        a0 = ffma2(w[2 * k],     hv.x, a0);
        a1 = ffma2(w[2 * k + 1], hv.y, a1);
    }
    float x0, y0, x1, y1;
    unpack2(a0, x0, y0);
    unpack2(a1, x1, y1);
    return (x0 + x1) + (y0 + y1);
}

// ---------------- release/acquire flags ----------------
__device__ __forceinline__ void flag_store(int* p, int v) {
    asm volatile("st.release.gpu.global.b32 [%0], %1;" :: "l"(p), "r"(v) : "memory");
}
__device__ __forceinline__ int flag_load(const int* p) {
    int v;
    asm volatile("ld.acquire.gpu.global.b32 %0, [%1];" : "=r"(v) : "l"(p) : "memory");
    return v;
}
__device__ __forceinline__ void wait_ge(const int* p, int target) {
    while (flag_load(p) < target) { __nanosleep(32); }
}

__global__ void reset_kernel() {
    int i = threadIdx.x;
    if (i < BB)     g_prog0[i] = 0;
    if (i < 2 * BB) g_progx[i] = 0;
    if (i < BB)     g_prog1[i] = 0;
}

// =====================================================================
// Mega-kernel: 40 blocks x 384 threads, all wave-1 co-resident.
//   0..7   : layer-0 recurrence (1 batch each)
//   8..23  : xp1 workers (2 per batch, parity interleave)
//   24..31 : layer-1 recurrence (1 batch each)
//   32..39 : head workers (1 per batch)
// Recurrence mapping: thread g owns gate-row g (quad = g/96, unit = g%96).
// Epilogue threads = g<96 (i-gate rows): iv stays in-register.
// =====================================================================
__global__ void __launch_bounds__(NT, 1)
mega_kernel(const float* __restrict__ x,
            const float* __restrict__ Wih0, const float* __restrict__ Whh0,
            const float* __restrict__ bv0,
            const float* __restrict__ Wih1, const float* __restrict__ Whh1,
            const float* __restrict__ bv1,
            const float* __restrict__ h0in, const float* __restrict__ c0in,
            const float* __restrict__ head_w, const float* __restrict__ head_b,
            float* __restrict__ out)
{
    __shared__ __align__(16) float sh[KW * HH];   // 6 KB; recurrences use sh[0..384)
    const int bid = blockIdx.x;
    const int g   = threadIdx.x;

    if (bid < 8) {
        // ======== layer-0 recurrence, batch b ========
        const int b    = bid;
        const int quad = g / HH;          // warp-uniform (96 = 3 warps)
        float* gsh = sh + HH;             // f/g/o activations, 288 floats

        ull w[48];
        load_row(w, Whh0 + g * HH);
        const float wih  = __ldg(&Wih0[g]);
        const float bias = __ldg(&bv0[g]);

        float c = 0.0f;
        if (g < HH) { sh[g] = __ldg(&h0in[g]); c = __ldg(&c0in[g]); }
        __syncthreads();

        const float* xb = x + (size_t)b * SEQ;
        float* hb_t = g_h0seq + (size_t)b * SEQ * HH;
        float xnext = __ldg(&xb[0]);

#pragma unroll 1
        for (int t = 0; t < SEQ; t++) {
            float xt = xnext;
            xnext = __ldg(&xb[min(t + 1, SEQ - 1)]);

            float dot = dotv(w, sh, fmaf(xt, wih, bias));
            float act = (quad == 2) ? tanh_f(dot) : sigmoid_f(dot);
            if (quad != 0) gsh[g - HH] = act;
            __syncthreads();                     // gates visible

            if (quad == 0) {
                float fv = gsh[g];
                float gv = gsh[g + HH];
                float ov = gsh[g + 2 * HH];
                c = fmaf(fv, c, act * gv);       // act == iv
                float hval = ov * tanh_f(c);
                sh[g]   = hval;
                hb_t[g] = hval;
            }
            __syncthreads();                     // h visible
            if (((t & (KW - 1)) == (KW - 1)) && g == GG - 1)
                flag_store(&g_prog0[b], t + 1);  // fire-and-forget release
            hb_t += HH;
        }
    } else if (bid < 24) {
        // ======== xp1 workers: 2 per batch ========
        const int i   = bid - 8;
        const int b   = i >> 1;
        const int par = i & 1;

        ull w[48];
        load_row(w, Wih1 + g * HH);
        const float bias = __ldg(&bv1[g]);

        const float* hbase = g_h0seq + (size_t)b * SEQ * HH;
        float* xpb = g_xp1 + (size_t)b * SEQ * GG;

#pragma unroll 1
        for (int t0 = par * KW; t0 < SEQ; t0 += 2 * KW) {
            if (g == 0) wait_ge(&g_prog0[b], t0 + KW);
            __syncthreads();
            ((float4*)sh)[g] = ((const float4*)(hbase + (size_t)t0 * HH))[g];
            __syncthreads();
            float* xpt = xpb + (size_t)t0 * GG + g;
#pragma unroll 4
            for (int s = 0; s < KW; s++) {
                xpt[0] = dotv(w, sh + s * HH, bias);
                xpt += GG;
            }
            __syncthreads();
            if (g == 0) flag_store(&g_progx[par * BB + b], t0 + KW);
        }
    } else if (bid < 32) {
        // ======== layer-1 recurrence, batch b ========
        const int b    = bid - 24;
        const int quad = g / HH;
        float* gsh = sh + HH;

        ull w[48];
        load_row(w, Whh1 + g * HH);

        float c = 0.0f;
        if (g < HH) { sh[g] = __ldg(&h0in[HH + g]); c = __ldg(&c0in[HH + g]); }
        __syncthreads();

        const float* xpr = g_xp1 + (size_t)b * SEQ * GG + g;
        float* hb_t = g_h1seq + (size_t)b * SEQ * HH;

#pragma unroll 1
        for (int t0 = 0; t0 < SEQ; t0 += KW) {
            const int par = (t0 >> 4) & 1;      // (t0/KW)&1 with KW=16
            if (g == 0) wait_ge(&g_progx[par * BB + b], t0 + KW);
            __syncthreads();

            float xpn = xpr[0];
#pragma unroll 1
            for (int tt = 0; tt < KW; tt++) {
                float xp = xpn;
                xpn = xpr[(tt + 1 < KW) ? GG : 0];   // prefetch within chunk

                float dot = dotv(w, sh, xp);
                float act = (quad == 2) ? tanh_f(dot) : sigmoid_f(dot);
                if (quad != 0) gsh[g - HH] = act;
                __syncthreads();

                if (quad == 0) {
                    float fv = gsh[g];
                    float gv = gsh[g + HH];
                    float ov = gsh[g + 2 * HH];
                    c = fmaf(fv, c, act * gv);
                    float hval = ov * tanh_f(c);
                    sh[g]   = hval;
                    hb_t[g] = hval;
                }
                __syncthreads();
                hb_t += HH;
                xpr  += GG;
            }
            if (g == GG - 1) flag_store(&g_prog1[b], t0 + KW);
        }
    } else {
        // ======== head workers ========
        const int b = bid - 32;
        float4 wv[24];
        const float4* wp = (const float4*)head_w;
#pragma unroll
        for (int k = 0; k < 24; k++) wv[k] = __ldg(&wp[k]);
        const float hb0 = __ldg(&head_b[0]);
        const float* h1b = g_h1seq + (size_t)b * SEQ * HH;
        float* ob = out + (size_t)b * SEQ;

#pragma unroll 1
        for (int t0 = 0; t0 < SEQ; t0 += HC) {
            if (g == 0) wait_ge(&g_prog1[b], t0 + HC);
            __syncthreads();
            if (g < HC) {
                const float4* hp = (const float4*)(h1b + (size_t)(t0 + g) * HH);
                float acc = 0.0f;
#pragma unroll
                for (int k = 0; k < 24; k++) {
                    float4 a = hp[k];
                    acc += a.x * wv[k].x + a.y * wv[k].y + a.z * wv[k].z + a.w * wv[k].w;
                }
                ob[t0 + g] = acc + hb0;
            }
        }
    }
}

extern "C" void kernel_launch(void* const* d_in, const int* in_sizes, int n_in,
                              void* d_out, int out_size)
{
    (void)in_sizes; (void)n_in; (void)out_size;
    const float* x      = (const float*)d_in[0];
    const float* W_ih_0 = (const float*)d_in[1];
    const float* W_hh_0 = (const float*)d_in[2];
    const float* b_0    = (const float*)d_in[3];
    const float* W_ih_1 = (const float*)d_in[4];
    const float* W_hh_1 = (const float*)d_in[5];
    const float* b_1    = (const float*)d_in[6];
    const float* h0     = (const float*)d_in[7];
    const float* c0     = (const float*)d_in[8];
    const float* head_w = (const float*)d_in[9];
    const float* head_b = (const float*)d_in[10];
    float* out = (float*)d_out;

    reset_kernel<<<1, 32>>>();
    mega_kernel<<<40, NT>>>(x, W_ih_0, W_hh_0, b_0, W_ih_1, W_hh_1, b_1,
                            h0, c0, head_w, head_b, out);
}